// round 11
// baseline (speedup 1.0000x reference)
#include <cuda_runtime.h>
#include <cstdint>

static constexpr int NCOLS = 99;
static constexpr int TPB   = 256;     // warps 0-6 consumers, warp 7 lane0 producer
static constexpr int TILE  = 64;      // rows per stage
static constexpr int NS    = 2;       // pipeline stages
static constexpr int GRID  = 296;     // 2 CTAs/SM, single resident wave
static constexpr int NMAIN = 232;     // main-role CTAs (stream only)
static constexpr int NPREPC= 64;      // prep-role CTAs
static constexpr int ADJ   = 8;       // tile-units of prep work per prep CTA
static constexpr int NCONS = 224;
static constexpr uint32_t STG = TILE * NCOLS * 4;          // 25344 B
static constexpr int SMEM_TOTAL = 128 + 2 * NS * (int)STG; // 101504 B

// ---------------- device scratch (single memset(0), no allocation) ---------
struct Zeros {
    double   acc[3];
    unsigned hist[200];
    unsigned maxkey[10];
    unsigned cominkey[10];
    unsigned done[3];   // [0] prep minmax sync(64), [1] finalize ticket(296), [2] hist done(64)
};
__device__ Zeros gz;

__device__ __forceinline__ unsigned f2key(float f) {
    unsigned u = __float_as_uint(f);
    return (u & 0x80000000u) ? ~u : (u | 0x80000000u);
}
__device__ __forceinline__ float key2f(unsigned k) {
    unsigned u = (k & 0x80000000u) ? (k ^ 0x80000000u) : ~k;
    return __uint_as_float(u);
}

// ---------------- mbarrier / bulk-copy helpers ------------------------------
__device__ __forceinline__ uint32_t s2u(const void* p) {
    return (uint32_t)__cvta_generic_to_shared(p);
}
__device__ __forceinline__ void mbar_init(uint32_t m, uint32_t cnt) {
    asm volatile("mbarrier.init.shared.b64 [%0], %1;" :: "r"(m), "r"(cnt) : "memory");
}
__device__ __forceinline__ void mbar_expect_tx(uint32_t m, uint32_t bytes) {
    asm volatile("mbarrier.arrive.expect_tx.shared.b64 _, [%0], %1;"
                 :: "r"(m), "r"(bytes) : "memory");
}
__device__ __forceinline__ void mbar_arrive(uint32_t m) {
    asm volatile("mbarrier.arrive.shared.b64 _, [%0];" :: "r"(m) : "memory");
}
__device__ __forceinline__ void mbar_wait(uint32_t m, uint32_t parity) {
    asm volatile(
        "{\n\t.reg .pred P;\n\t"
        "WL_%=:\n\t"
        "mbarrier.try_wait.parity.acquire.cta.shared::cta.b64 P, [%0], %1, 0x989680;\n\t"
        "@P bra.uni WD_%=;\n\t"
        "bra.uni WL_%=;\n\t"
        "WD_%=:\n\t}"
        :: "r"(m), "r"(parity) : "memory");
}
__device__ __forceinline__ void bulk_g2s(uint32_t dst, const void* src,
                                         uint32_t bytes, uint32_t mbar) {
    asm volatile(
        "cp.async.bulk.shared::cluster.global.mbarrier::complete_tx::bytes "
        "[%0], [%1], %2, [%3];"
        :: "r"(dst), "l"(src), "r"(bytes), "r"(mbar) : "memory");
}

// ---------------- math helpers ----------------------------------------------
template <int S, int E>
__device__ __forceinline__ float lse_blk(const float* row) {
    float s = 0.f;
#pragma unroll
    for (int c = S; c < E; ++c) s += __expf(row[c]);
    return __logf(s);
}
__device__ __forceinline__ bool quad_rare(int c0) {
    return (c0 == 0) | ((unsigned)(c0 - 52) <= 5u) | (c0 >= 96);
}
__device__ __forceinline__ void acc4(
    float4 d, float4 x, int c0,
    float& dot0, float& dot1, float& mse, float& dotc)
{
    dot0 = fmaf(d.x, x.x, dot0);
    dot1 = fmaf(d.y, x.y, dot1);
    dot0 = fmaf(d.z, x.z, dot0);
    dot1 = fmaf(d.w, x.w, dot1);
    if (quad_rare(c0)) {
        float dv[4] = {d.x, d.y, d.z, d.w};
        float xv[4] = {x.x, x.y, x.z, x.w};
        int c = c0;
#pragma unroll
        for (int j = 0; j < 4; j++) {
            bool cont = (c == 0) | ((unsigned)(c - 55) <= 2u);
            if (cont) {
                float df = dv[j] - xv[j];
                mse  = fmaf(df, df, mse);
                dotc = fmaf(dv[j], xv[j], dotc);
            }
            if (++c == NCOLS) c = 0;
        }
    }
}

// ---------------- fused kernel ----------------------------------------------
__global__ void __launch_bounds__(TPB, 2)
k_fused(const float4* __restrict__ e4,
        const float* __restrict__ dec, const float* __restrict__ tru,
        float* __restrict__ out, int B) {
    extern __shared__ char dsm[];   // [128 mbars][NS dec stages][NS tru stages]
    __shared__ float s_mn[8][10], s_mx[8][10];
    __shared__ unsigned sh[200];
    __shared__ float smn[10], swid[10];
    __shared__ float wr[3][TPB / 32];
    __shared__ int   s_last;

    const int t = threadIdx.x, lane = t & 31, w = t >> 5;
    const int bx = blockIdx.x;
    const uint32_t mb    = s2u(dsm);
    const uint32_t full0  = mb;             // full[s]  at +8s
    const uint32_t empty0 = mb + 64;        // empty[s] at +64+8s
    const uint32_t decS0  = mb + 128;
    const uint32_t truS0  = mb + 128 + NS * STG;

    if (t == 0) {
#pragma unroll
        for (int s = 0; s < NS; s++) {
            mbar_init(full0  + 8u * s, 1u);
            mbar_init(empty0 + 8u * s, 7u);    // one arrival per consumer warp
        }
        asm volatile("fence.proxy.async.shared::cta;" ::: "memory");
    }
    __syncthreads();

    // ================= PREP ROLE (CTAs [NMAIN, GRID)) =================
    if (bx >= NMAIN) {
        const int stride = NPREPC * TPB;
        const int gbase  = (bx - NMAIN) * TPB + t;

        float mn[10], mx[10];
        const float INF = __int_as_float(0x7f800000);
#pragma unroll
        for (int i = 0; i < 10; i++) { mn[i] = INF; mx[i] = -INF; }
        for (int r = gbase; r < B; r += 2 * stride) {
            float4 a0 = e4[3*r], b0 = e4[3*r+1], c0 = e4[3*r+2];
            int r1 = r + stride;
            bool ok1 = r1 < B;
            float4 a1, b1, c1;
            if (ok1) { a1 = e4[3*r1]; b1 = e4[3*r1+1]; c1 = e4[3*r1+2]; }
            float v0[10] = {a0.x,a0.y,a0.z,a0.w,b0.x,b0.y,b0.z,b0.w,c0.x,c0.y};
#pragma unroll
            for (int i = 0; i < 10; i++) {
                mn[i] = fminf(mn[i], v0[i]);
                mx[i] = fmaxf(mx[i], v0[i]);
            }
            if (ok1) {
                float v1[10] = {a1.x,a1.y,a1.z,a1.w,b1.x,b1.y,b1.z,b1.w,c1.x,c1.y};
#pragma unroll
                for (int i = 0; i < 10; i++) {
                    mn[i] = fminf(mn[i], v1[i]);
                    mx[i] = fmaxf(mx[i], v1[i]);
                }
            }
        }
#pragma unroll
        for (int i = 0; i < 10; i++) {
#pragma unroll
            for (int o = 16; o > 0; o >>= 1) {
                mn[i] = fminf(mn[i], __shfl_xor_sync(0xFFFFFFFFu, mn[i], o));
                mx[i] = fmaxf(mx[i], __shfl_xor_sync(0xFFFFFFFFu, mx[i], o));
            }
        }
        if (lane == 0) {
#pragma unroll
            for (int i = 0; i < 10; i++) { s_mn[w][i] = mn[i]; s_mx[w][i] = mx[i]; }
        }
        for (int j = t; j < 200; j += TPB) sh[j] = 0u;
        __syncthreads();
        if (t < 10) {
            float m = s_mn[0][t], x = s_mx[0][t];
#pragma unroll
            for (int ww = 1; ww < 8; ww++) { m = fminf(m, s_mn[ww][t]); x = fmaxf(x, s_mx[ww][t]); }
            atomicMax(&gz.cominkey[t], ~f2key(m));
            atomicMax(&gz.maxkey[t],    f2key(x));
        }

        __threadfence();
        __syncthreads();
        if (t == 0) {
            atomicAdd(&gz.done[0], 1u);
            while (atomicAdd(&gz.done[0], 0u) < (unsigned)NPREPC) __nanosleep(64);
        }
        __syncthreads();
        __threadfence();

        if (t < 10) {
            float m = key2f(~gz.cominkey[t]);
            float x = key2f( gz.maxkey[t]);
            smn[t]  = m;
            swid[t] = fmaxf(x - m, 1e-12f);
        }
        __syncthreads();

        const int B_al = B & ~31;
        for (int r = gbase; r < B_al; r += stride) {
            float4 a = e4[3*r], b = e4[3*r+1], c = e4[3*r+2];
            unsigned base = (c.w == 0.0f) ? 0u : 100u;   // col 11 = sex
            float v[10] = {a.x,a.y,a.z,a.w,b.x,b.y,b.z,b.w,c.x,c.y};
#pragma unroll
            for (int i = 0; i < 10; i++) {
                float tt = (v[i] - smn[i]) / swid[i] * 10.0f;
                int bi = (int)floorf(tt);
                bi = bi < 0 ? 0 : (bi > 9 ? 9 : bi);
                unsigned key = base + (unsigned)(i * 10 + bi);
                unsigned msk = __match_any_sync(0xFFFFFFFFu, key);
                if ((msk & ((1u << lane) - 1u)) == 0u)
                    atomicAdd(&sh[key], (unsigned)__popc(msk));
            }
        }
        for (int r = B_al + gbase; r < B; r += stride) {
            float4 a = e4[3*r], b = e4[3*r+1], c = e4[3*r+2];
            unsigned base = (c.w == 0.0f) ? 0u : 100u;
            float v[10] = {a.x,a.y,a.z,a.w,b.x,b.y,b.z,b.w,c.x,c.y};
#pragma unroll
            for (int i = 0; i < 10; i++) {
                float tt = (v[i] - smn[i]) / swid[i] * 10.0f;
                int bi = (int)floorf(tt);
                bi = bi < 0 ? 0 : (bi > 9 ? 9 : bi);
                atomicAdd(&sh[base + (unsigned)(i * 10 + bi)], 1u);
            }
        }
        __syncthreads();
        for (int j = t; j < 200; j += TPB)
            if (sh[j]) atomicAdd(&gz.hist[j], sh[j]);
        __threadfence();
        __syncthreads();
        if (t == 0) atomicAdd(&gz.done[2], 1u);
        // falls through to tile pipeline with reduced share
    }

    // ================= STATIC WEIGHTED TILE SPLIT =================
    const int NT = B / TILE;                 // full tiles only
    int q  = (NT + NPREPC * ADJ) / GRID;
    int Tp = q - ADJ; if (Tp < 0) Tp = 0;
    int mainShare = NT - NPREPC * Tp;
    int Tm  = mainShare / NMAIN;
    int rem = mainShare - Tm * NMAIN;
    long start; int myN;
    if (bx < NMAIN) {
        start = (long)bx * Tm + (bx < rem ? bx : rem);
        myN   = Tm + (bx < rem ? 1 : 0);
    } else {
        start = (long)NMAIN * Tm + rem + (long)(bx - NMAIN) * Tp;
        myN   = Tp;
    }

    float dot0 = 0.f, dot1 = 0.f, a_mse = 0.f, dotc = 0.f, a_lse = 0.f;

    if (t == NCONS) {
        // -------- producer (warp 7 lane 0) --------
        int ps = 0; uint32_t pp = 1;
        const char* decB = (const char*)dec;
        const char* truB = (const char*)tru;
        for (int n = 0; n < myN; n++) {
            mbar_wait(empty0 + 8u * ps, pp);
            mbar_expect_tx(full0 + 8u * ps, 2u * STG);
            size_t off = (size_t)(start + n) * STG;
            bulk_g2s(decS0 + (uint32_t)ps * STG, decB + off, STG, full0 + 8u * ps);
            bulk_g2s(truS0 + (uint32_t)ps * STG, truB + off, STG, full0 + 8u * ps);
            if (++ps == NS) { ps = 0; pp ^= 1u; }
        }
    } else if (t < NCONS) {
        // -------- consumers (224 threads, warps 0-6) --------
        int cs = 0; uint32_t cp = 0;
        const int row  = t >> 1;          // LSE rows for t<128
        const int half = t & 1;
        const int cst  = (4 * t) % NCOLS; // phase-A start col; +5 mod 99 per step
        constexpr int N4 = TILE * NCOLS / 4;   // 1584
        for (int n = 0; n < myN; n++) {
            mbar_wait(full0 + 8u * cs, cp);
            const float*  D  = (const float*)(dsm + 128 + cs * (int)STG);
            const float4* D4 = (const float4*)D;
            const float4* X4 = (const float4*)(dsm + 128 + NS * (int)STG + cs * (int)STG);

            int c0 = cst;
            for (int i4 = t; i4 < N4; i4 += NCONS) {
                acc4(D4[i4], X4[i4], c0, dot0, dot1, a_mse, dotc);
                c0 += 5; if (c0 >= NCOLS) c0 -= NCOLS;
            }
            if (t < 2 * TILE) {
                const float* rp = D + row * NCOLS;
                if (half == 0) {
                    a_lse += lse_blk< 1,  8>(rp);
                    a_lse += lse_blk< 8, 24>(rp);
                    a_lse += lse_blk<24, 31>(rp);
                    a_lse += lse_blk<31, 45>(rp);
                } else {
                    a_lse += lse_blk<45, 51>(rp);
                    a_lse += lse_blk<51, 53>(rp);
                    a_lse += lse_blk<53, 55>(rp);
                    a_lse += lse_blk<58, 99>(rp);
                }
            }
            __syncwarp();
            if (lane == 0) mbar_arrive(empty0 + 8u * cs);
            if (++cs == NS) { cs = 0; cp ^= 1u; }
        }
    }

    // leftover rows (B % TILE) handled by CTA 0 consumers from global
    if (bx == 0 && t < NCONS) {
        int r = NT * TILE + t;
        if (r < B) {
            const float* Dp = dec + (size_t)r * NCOLS;
            const float* Xp = tru + (size_t)r * NCOLS;
            for (int c = 0; c < NCOLS; c++) {
                float d = Dp[c], x = Xp[c];
                bool cont = (c == 0) | ((unsigned)(c - 55) <= 2u);
                dot0 = fmaf(d, x, dot0);
                if (cont) { float df = d - x; a_mse = fmaf(df, df, a_mse); dotc = fmaf(d, x, dotc); }
            }
            a_lse += lse_blk< 1,  8>(Dp);
            a_lse += lse_blk< 8, 24>(Dp);
            a_lse += lse_blk<24, 31>(Dp);
            a_lse += lse_blk<31, 45>(Dp);
            a_lse += lse_blk<45, 51>(Dp);
            a_lse += lse_blk<51, 53>(Dp);
            a_lse += lse_blk<53, 55>(Dp);
            a_lse += lse_blk<58, 99>(Dp);
        }
    }

    // ---- block reduce -> double global atomics ----
    float a_dot = (dot0 + dot1) - dotc;
#pragma unroll
    for (int o = 16; o > 0; o >>= 1) {
        a_mse += __shfl_xor_sync(0xFFFFFFFFu, a_mse, o);
        a_dot += __shfl_xor_sync(0xFFFFFFFFu, a_dot, o);
        a_lse += __shfl_xor_sync(0xFFFFFFFFu, a_lse, o);
    }
    if (lane == 0) { wr[0][w] = a_mse; wr[1][w] = a_dot; wr[2][w] = a_lse; }
    __syncthreads();
    if (t == 0) {
        float m = 0.f, d = 0.f, l = 0.f;
#pragma unroll
        for (int k = 0; k < TPB / 32; k++) { m += wr[0][k]; d += wr[1][k]; l += wr[2][k]; }
        atomicAdd(&gz.acc[0], (double)m);
        atomicAdd(&gz.acc[1], (double)d);
        atomicAdd(&gz.acc[2], (double)l);
        __threadfence();
        unsigned tk = atomicAdd(&gz.done[1], 1u);
        s_last = (tk == (unsigned)(GRID - 1)) ? 1 : 0;
        if (s_last) {
            while (atomicAdd(&gz.done[2], 0u) < (unsigned)NPREPC) __nanosleep(64);
        }
    }
    __syncthreads();

    // ---- last CTA finalizes (double precision, 32 lanes) ----
    if (s_last && t < 32) {
        __threadfence();
        int lane32 = t;
        double mcnt = (lane32 < 10) ? (double)gz.hist[lane32]       : 0.0;
        double fcnt = (lane32 < 10) ? (double)gz.hist[100 + lane32] : 0.0;
#pragma unroll
        for (int o = 16; o > 0; o >>= 1) {
            mcnt += __shfl_xor_sync(0xFFFFFFFFu, mcnt, o);
            fcnt += __shfl_xor_sync(0xFFFFFFFFu, fcnt, o);
        }
        double mc = fmax(mcnt, 1.0), fc = fmax(fcnt, 1.0);
        double kld = 0.0;
#pragma unroll
        for (int k = 0; k < 4; k++) {
            int b = k * 32 + lane32;
            if (b < 100) {
                double p2 = (double)gz.hist[b] / mc;
                double q2 = (double)gz.hist[100 + b] / fc;
                if (p2 > 0.0 && q2 > 0.0) kld += p2 * log(p2 / q2);
            }
        }
#pragma unroll
        for (int o = 16; o > 0; o >>= 1)
            kld += __shfl_xor_sync(0xFFFFFFFFu, kld, o);
        if (lane32 == 0) {
            double mseS = atomicAdd(&gz.acc[0], 0.0);
            double dotS = atomicAdd(&gz.acc[1], 0.0);
            double lseS = atomicAdd(&gz.acc[2], 0.0);
            double fB   = (double)B;
            double mse  = mseS / fB;
            double ce   = (lseS - dotS) / fB;
            double akld = 0.5 * kld;
            out[0] = (float)(0.5 * (mse + ce) + akld);
            out[1] = (float)mse;
            out[2] = (float)ce;
            out[3] = (float)akld;
        }
    }
}

// ---------------- launcher ----------------
extern "C" void kernel_launch(void* const* d_in, const int* in_sizes, int n_in,
                              void* d_out, int out_size) {
    const float* enc = (const float*)d_in[0];   // [B,12]
    const float* dec = (const float*)d_in[1];   // [B,99]
    const float* tru = (const float*)d_in[2];   // [B,99]
    const int B = in_sizes[1] / NCOLS;
    float* out = (float*)d_out;

    void* pz = nullptr;
    cudaGetSymbolAddress(&pz, gz);
    cudaMemsetAsync(pz, 0, sizeof(Zeros), 0);

    cudaFuncSetAttribute(k_fused, cudaFuncAttributeMaxDynamicSharedMemorySize, SMEM_TOTAL);

    k_fused<<<GRID, TPB, SMEM_TOTAL>>>((const float4*)enc, dec, tru, out, B);
}

// round 12
// speedup vs baseline: 1.1909x; 1.1909x over previous
#include <cuda_runtime.h>
#include <cuda_fp16.h>

static constexpr int NCOLS = 99;
static constexpr int TPB   = 128;   // threads per block
static constexpr int TILE  = 128;   // rows per tile
static constexpr int NPREP = 296;   // prep-role CTAs (first in grid)

// ---------------- device scratch (single memset(0), no allocation) ---------
struct Zeros {
    double   acc[3];        // [0]=mse sum, [1]=dot sum (ce cols), [2]=lse sum
    unsigned hist[200];     // [sex(2)][feat(10)][bin(10)]
    unsigned maxkey[10];    // atomicMax of key(x)
    unsigned cominkey[10];  // atomicMax of ~key(x)  (== complemented min)
    unsigned done[3];       // [0]: prep minmax sync, [1]: tile ticket, [2]: prep hist done
};
__device__ Zeros gz;

// monotonic float<->uint key
__device__ __forceinline__ unsigned f2key(float f) {
    unsigned u = __float_as_uint(f);
    return (u & 0x80000000u) ? ~u : (u | 0x80000000u);
}
__device__ __forceinline__ float key2f(unsigned k) {
    unsigned u = (k & 0x80000000u) ? (k ^ 0x80000000u) : ~k;
    return __uint_as_float(u);
}

// ---------------- half2-vectorized LSE --------------------------------------
// Segment [S,E) of a row whose base half-offset has parity P (= row & 1,
// since 99*row = row mod 2). Pairs must start at column c with c === P (mod 2)
// so that (99*row + c) is even -> LDS.32-aligned __half2 loads.
template <int S, int E, int P>
__device__ __forceinline__ float lse_seg(const __half* row) {
    constexpr int PS = ((S & 1) == P) ? S : S + 1;          // first pair start
    constexpr int NP = (PS + 1 < E) ? (E - PS) / 2 : 0;     // number of pairs
    constexpr int TS = PS + 2 * NP;                          // tail scalar col
    float s = 0.f;
    if (S < PS) s += __expf(__half2float(row[S]));           // head scalar
    if (NP > 0) {
        const __half2* r2 = reinterpret_cast<const __half2*>(row + PS);
        __half2 acc = __float2half2_rn(0.f);
#pragma unroll
        for (int p = 0; p < NP; p++) acc = __hadd2(acc, h2exp(r2[p]));
        float2 f = __half22float2(acc);
        s += f.x + f.y;
    }
    if (TS < E) s += __expf(__half2float(row[TS]));          // tail scalar
    return __logf(s);
}

template <int P>
__device__ __forceinline__ float lse_row(const __half* row) {
    float a = 0.f;
    a += lse_seg< 1,  8, P>(row);
    a += lse_seg< 8, 24, P>(row);
    a += lse_seg<24, 31, P>(row);
    a += lse_seg<31, 45, P>(row);
    a += lse_seg<45, 51, P>(row);
    a += lse_seg<51, 53, P>(row);
    a += lse_seg<53, 55, P>(row);
    a += lse_seg<58, 99, P>(row);
    return a;
}

// ---------------- other helpers ---------------------------------------------
__device__ __forceinline__ bool quad_rare(int c0) {
    return (c0 == 0) | ((unsigned)(c0 - 52) <= 5u) | (c0 >= 96);
}
__device__ __forceinline__ int wrap99(int c) { return (c >= NCOLS) ? c - NCOLS : c; }

// consume one float4-pair: fp16 store + dotAll FFMAs + rare cont-col fixup
__device__ __forceinline__ void consume(
    float4 d, float4 t, int c0, __half* smh, int i,
    float& dot0, float& dot1, float& mse, float& dotc)
{
    union { __half2 h[2]; uint2 u; } pk;
    pk.h[0] = __floats2half2_rn(d.x, d.y);
    pk.h[1] = __floats2half2_rn(d.z, d.w);
    *reinterpret_cast<uint2*>(smh + 4 * i) = pk.u;   // 8B aligned
    dot0 = fmaf(d.x, t.x, dot0);
    dot1 = fmaf(d.y, t.y, dot1);
    dot0 = fmaf(d.z, t.z, dot0);
    dot1 = fmaf(d.w, t.w, dot1);
    if (quad_rare(c0)) {
        float dv[4] = {d.x, d.y, d.z, d.w};
        float tv[4] = {t.x, t.y, t.z, t.w};
        int c = c0;
#pragma unroll
        for (int j = 0; j < 4; j++) {
            bool cont = (c == 0) | ((unsigned)(c - 55) <= 2u);
            if (cont) {
                float df = dv[j] - tv[j];
                mse  = fmaf(df, df, mse);
                dotc = fmaf(dv[j], tv[j], dotc);   // subtract later
            }
            if (++c == NCOLS) c = 0;
        }
    }
}

// ---------------- fused kernel ---------------------------------------------
__global__ void __launch_bounds__(TPB, 8)
k_fused(const float4* __restrict__ e4,
        const float* __restrict__ dec, const float* __restrict__ tru,
        float* __restrict__ out, int B) {
    __shared__ __align__(8) __half smh[TILE * NCOLS];   // 25344 B (tile role)
    __shared__ float wr[3][TPB / 32];
    __shared__ int   s_last;
    __shared__ float s_mn[4][10], s_mx[4][10]; // prep role
    __shared__ unsigned sh[200];
    __shared__ float smn[10], swid[10];

    const int t = threadIdx.x, lane = t & 31, w = t >> 5;

    if (blockIdx.x < NPREP) {
        // ================= PREP ROLE =================
        const int stride = NPREP * TPB;
        const int gbase  = blockIdx.x * TPB + t;

        float mn[10], mx[10];
        const float INF = __int_as_float(0x7f800000);
#pragma unroll
        for (int i = 0; i < 10; i++) { mn[i] = INF; mx[i] = -INF; }
        for (int r = gbase; r < B; r += 2 * stride) {
            float4 a0 = e4[3*r], b0 = e4[3*r+1], c0 = e4[3*r+2];
            int r1 = r + stride;
            bool ok1 = r1 < B;
            float4 a1, b1, c1;
            if (ok1) { a1 = e4[3*r1]; b1 = e4[3*r1+1]; c1 = e4[3*r1+2]; }
            float v0[10] = {a0.x,a0.y,a0.z,a0.w,b0.x,b0.y,b0.z,b0.w,c0.x,c0.y};
#pragma unroll
            for (int i = 0; i < 10; i++) {
                mn[i] = fminf(mn[i], v0[i]);
                mx[i] = fmaxf(mx[i], v0[i]);
            }
            if (ok1) {
                float v1[10] = {a1.x,a1.y,a1.z,a1.w,b1.x,b1.y,b1.z,b1.w,c1.x,c1.y};
#pragma unroll
                for (int i = 0; i < 10; i++) {
                    mn[i] = fminf(mn[i], v1[i]);
                    mx[i] = fmaxf(mx[i], v1[i]);
                }
            }
        }
#pragma unroll
        for (int i = 0; i < 10; i++) {
#pragma unroll
            for (int o = 16; o > 0; o >>= 1) {
                mn[i] = fminf(mn[i], __shfl_xor_sync(0xFFFFFFFFu, mn[i], o));
                mx[i] = fmaxf(mx[i], __shfl_xor_sync(0xFFFFFFFFu, mx[i], o));
            }
        }
        if (lane == 0) {
#pragma unroll
            for (int i = 0; i < 10; i++) { s_mn[w][i] = mn[i]; s_mx[w][i] = mx[i]; }
        }
        for (int j = t; j < 200; j += TPB) sh[j] = 0u;
        __syncthreads();
        if (t < 10) {
            float m = s_mn[0][t], x = s_mx[0][t];
#pragma unroll
            for (int ww = 1; ww < 4; ww++) { m = fminf(m, s_mn[ww][t]); x = fmaxf(x, s_mx[ww][t]); }
            atomicMax(&gz.cominkey[t], ~f2key(m));
            atomicMax(&gz.maxkey[t],    f2key(x));
        }

        __threadfence();
        __syncthreads();
        if (t == 0) {
            atomicAdd(&gz.done[0], 1u);
            while (atomicAdd(&gz.done[0], 0u) < (unsigned)NPREP) __nanosleep(64);
        }
        __syncthreads();
        __threadfence();

        if (t < 10) {
            float m = key2f(~gz.cominkey[t]);
            float x = key2f( gz.maxkey[t]);
            smn[t]  = m;
            swid[t] = fmaxf(x - m, 1e-12f);
        }
        __syncthreads();

        const int B_al = B & ~31;
        for (int r = gbase; r < B_al; r += stride) {
            float4 a = e4[3*r], b = e4[3*r+1], c = e4[3*r+2];
            unsigned base = (c.w == 0.0f) ? 0u : 100u;   // col 11 = sex
            float v[10] = {a.x,a.y,a.z,a.w,b.x,b.y,b.z,b.w,c.x,c.y};
#pragma unroll
            for (int i = 0; i < 10; i++) {
                float tt = (v[i] - smn[i]) / swid[i] * 10.0f;
                int bi = (int)floorf(tt);
                bi = bi < 0 ? 0 : (bi > 9 ? 9 : bi);
                unsigned key = base + (unsigned)(i * 10 + bi);
                unsigned msk = __match_any_sync(0xFFFFFFFFu, key);
                if ((msk & ((1u << lane) - 1u)) == 0u)
                    atomicAdd(&sh[key], (unsigned)__popc(msk));
            }
        }
        for (int r = B_al + gbase; r < B; r += stride) {
            float4 a = e4[3*r], b = e4[3*r+1], c = e4[3*r+2];
            unsigned base = (c.w == 0.0f) ? 0u : 100u;
            float v[10] = {a.x,a.y,a.z,a.w,b.x,b.y,b.z,b.w,c.x,c.y};
#pragma unroll
            for (int i = 0; i < 10; i++) {
                float tt = (v[i] - smn[i]) / swid[i] * 10.0f;
                int bi = (int)floorf(tt);
                bi = bi < 0 ? 0 : (bi > 9 ? 9 : bi);
                atomicAdd(&sh[base + (unsigned)(i * 10 + bi)], 1u);
            }
        }
        __syncthreads();
        for (int j = t; j < 200; j += TPB)
            if (sh[j]) atomicAdd(&gz.hist[j], sh[j]);
        __threadfence();
        __syncthreads();
        if (t == 0) atomicAdd(&gz.done[2], 1u);   // hist ticket
        return;
    }

    // ================= TILE ROLE =================
    const int tileIdx = blockIdx.x - NPREP;
    const int NT      = gridDim.x - NPREP;
    const int r0   = tileIdx * TILE;
    const int rows = min(TILE, B - r0);
    const int nflt = rows * NCOLS;
    const int n4   = nflt >> 2;
    const size_t ebase = (size_t)r0 * NCOLS;
    const float4* d4 = (const float4*)(dec + ebase);
    const float4* t4 = (const float4*)(tru + ebase);

    float dot0 = 0.f, dot1 = 0.f, a_mse = 0.f, dotc = 0.f;

    // columns: element 4*(tid + j*TPB): +17 mod 99 per j, +34 per 2-pair stage
    int cb = (4 * t) % NCOLS;
    const int NS = n4 / (2 * TPB);           // full 2-pair stages

    float4 da0, ta0, da1, ta1, db0, tb0, db1, tb1;
    int ia = t;
    if (NS > 0) {
        da0 = d4[ia];       ta0 = t4[ia];
        da1 = d4[ia + TPB]; ta1 = t4[ia + TPB];
    }
    for (int s = 0; s < NS; s += 2) {
        const int ib = ia + 2 * TPB;
        const bool hb = (s + 1) < NS;
        if (hb) { db0 = d4[ib]; tb0 = t4[ib]; db1 = d4[ib + TPB]; tb1 = t4[ib + TPB]; }
        consume(da0, ta0, cb,              smh, ia,       dot0, dot1, a_mse, dotc);
        consume(da1, ta1, wrap99(cb + 17), smh, ia + TPB, dot0, dot1, a_mse, dotc);
        cb = wrap99(cb + 34);
        if (!hb) break;
        const int ic = ib + 2 * TPB;
        const bool hc = (s + 2) < NS;
        if (hc) { da0 = d4[ic]; ta0 = t4[ic]; da1 = d4[ic + TPB]; ta1 = t4[ic + TPB]; }
        consume(db0, tb0, cb,              smh, ib,       dot0, dot1, a_mse, dotc);
        consume(db1, tb1, wrap99(cb + 17), smh, ib + TPB, dot0, dot1, a_mse, dotc);
        cb = wrap99(cb + 34);
        ia = ic;
    }
    for (int i = NS * 2 * TPB + t; i < n4; i += TPB) {
        consume(d4[i], t4[i], (4 * i) % NCOLS, smh, i, dot0, dot1, a_mse, dotc);
    }
    for (int e = (n4 << 2) + t; e < nflt; e += TPB) {   // float tail
        float d = dec[ebase + e], tt = tru[ebase + e];
        smh[e] = __float2half_rn(d);
        int c = e % NCOLS;
        bool cont = (c == 0) | ((unsigned)(c - 55) <= 2u);
        dot0 = fmaf(d, tt, dot0);
        if (cont) {
            float df = d - tt;
            a_mse = fmaf(df, df, a_mse);
            dotc  = fmaf(d, tt, dotc);
        }
    }
    __syncthreads();

    // phase 2: one thread per row, half2-vectorized LSE (parity-templated)
    float a_lse = 0.f;
    if (t < rows) {
        const __half* row = smh + t * NCOLS;
        if (t & 1) a_lse = lse_row<1>(row);
        else       a_lse = lse_row<0>(row);
    }

    // block reduce -> double global atomics
    float a_dot = (dot0 + dot1) - dotc;
#pragma unroll
    for (int o = 16; o > 0; o >>= 1) {
        a_mse += __shfl_xor_sync(0xFFFFFFFFu, a_mse, o);
        a_dot += __shfl_xor_sync(0xFFFFFFFFu, a_dot, o);
        a_lse += __shfl_xor_sync(0xFFFFFFFFu, a_lse, o);
    }
    if (lane == 0) { wr[0][w] = a_mse; wr[1][w] = a_dot; wr[2][w] = a_lse; }
    __syncthreads();
    if (t == 0) {
        float m = 0.f, d = 0.f, l = 0.f;
#pragma unroll
        for (int k = 0; k < TPB / 32; k++) { m += wr[0][k]; d += wr[1][k]; l += wr[2][k]; }
        atomicAdd(&gz.acc[0], (double)m);
        atomicAdd(&gz.acc[1], (double)d);
        atomicAdd(&gz.acc[2], (double)l);
        __threadfence();
        unsigned tk = atomicAdd(&gz.done[1], 1u);
        s_last = (tk == (unsigned)(NT - 1)) ? 1 : 0;
        if (s_last) {   // wait for prep histogram tickets
            while (atomicAdd(&gz.done[2], 0u) < (unsigned)NPREP) __nanosleep(64);
        }
    }
    __syncthreads();

    // last tile CTA finalizes (double precision, 32 lanes)
    if (s_last && t < 32) {
        __threadfence();
        int lane32 = t;
        double mcnt = (lane32 < 10) ? (double)gz.hist[lane32]       : 0.0;
        double fcnt = (lane32 < 10) ? (double)gz.hist[100 + lane32] : 0.0;
#pragma unroll
        for (int o = 16; o > 0; o >>= 1) {
            mcnt += __shfl_xor_sync(0xFFFFFFFFu, mcnt, o);
            fcnt += __shfl_xor_sync(0xFFFFFFFFu, fcnt, o);
        }
        double mc = fmax(mcnt, 1.0), fc = fmax(fcnt, 1.0);
        double kld = 0.0;
#pragma unroll
        for (int k = 0; k < 4; k++) {
            int b = k * 32 + lane32;
            if (b < 100) {
                double p = (double)gz.hist[b] / mc;
                double q = (double)gz.hist[100 + b] / fc;
                if (p > 0.0 && q > 0.0) kld += p * log(p / q);
            }
        }
#pragma unroll
        for (int o = 16; o > 0; o >>= 1)
            kld += __shfl_xor_sync(0xFFFFFFFFu, kld, o);
        if (lane32 == 0) {
            double mseS = atomicAdd(&gz.acc[0], 0.0);
            double dotS = atomicAdd(&gz.acc[1], 0.0);
            double lseS = atomicAdd(&gz.acc[2], 0.0);
            double fB   = (double)B;
            double mse  = mseS / fB;
            double ce   = (lseS - dotS) / fB;
            double akld = 0.5 * kld;
            out[0] = (float)(0.5 * (mse + ce) + akld);
            out[1] = (float)mse;
            out[2] = (float)ce;
            out[3] = (float)akld;
        }
    }
}

// ---------------- launcher ----------------
extern "C" void kernel_launch(void* const* d_in, const int* in_sizes, int n_in,
                              void* d_out, int out_size) {
    const float* enc = (const float*)d_in[0];   // [B,12]
    const float* dec = (const float*)d_in[1];   // [B,99]
    const float* tru = (const float*)d_in[2];   // [B,99]
    const int B = in_sizes[1] / NCOLS;
    float* out = (float*)d_out;

    void* pz = nullptr;
    cudaGetSymbolAddress(&pz, gz);
    cudaMemsetAsync(pz, 0, sizeof(Zeros), 0);

    cudaFuncSetAttribute(k_fused, cudaFuncAttributePreferredSharedMemoryCarveout, 100);

    const int NT   = (B + TILE - 1) / TILE;
    const int grid = NPREP + NT;
    k_fused<<<grid, TPB>>>((const float4*)enc, dec, tru, out, B);
}

// round 14
// speedup vs baseline: 1.2726x; 1.0686x over previous
#include <cuda_runtime.h>
#include <cuda_fp16.h>
#include <cstdint>

static constexpr int NCOLS = 99;
static constexpr int TPB   = 128;   // threads per block
static constexpr int TILE  = 128;   // rows per tile
static constexpr int NPREP = 296;   // prep-role CTAs (first in grid)

// ---------------- device scratch (single memset(0), no allocation) ---------
struct Zeros {
    double   acc[3];        // [0]=mse sum, [1]=dot sum (ce cols), [2]=lse sum
    unsigned hist[200];     // [sex(2)][feat(10)][bin(10)]
    unsigned maxkey[10];    // atomicMax of key(x)
    unsigned cominkey[10];  // atomicMax of ~key(x)  (== complemented min)
    unsigned done[3];       // [0]: prep minmax sync, [1]: tile ticket, [2]: prep hist done
};
__device__ Zeros gz;

// monotonic float<->uint key
__device__ __forceinline__ unsigned f2key(float f) {
    unsigned u = __float_as_uint(f);
    return (u & 0x80000000u) ? ~u : (u | 0x80000000u);
}
__device__ __forceinline__ float key2f(unsigned k) {
    unsigned u = (k & 0x80000000u) ? (k ^ 0x80000000u) : ~k;
    return __uint_as_float(u);
}

// ---------------- hardware ex2 helpers --------------------------------------
// smem holds y = x * log2(e) in fp16, so exp(x) = 2^y.
__device__ __forceinline__ __half2 ex2_h2(__half2 v) {
    unsigned int in = *reinterpret_cast<unsigned int*>(&v), out;
    asm("ex2.approx.f16x2 %0, %1;" : "=r"(out) : "r"(in));
    return *reinterpret_cast<__half2*>(&out);
}
__device__ __forceinline__ float ex2_s(__half v) {
    float f = __half2float(v), r;
    asm("ex2.approx.f32 %0, %1;" : "=f"(r) : "f"(f));
    return r;
}

// ---------------- half2-vectorized LSE (hardware ex2) ------------------------
// Segment [S,E) of a row whose base half-offset has parity P (= row & 1).
// Pairs start at column c with c === P (mod 2) -> LDS.32-aligned __half2.
template <int S, int E, int P>
__device__ __forceinline__ float lse_seg(const __half* row) {
    constexpr int PS = ((S & 1) == P) ? S : S + 1;          // first pair start
    constexpr int NP = (PS + 1 < E) ? (E - PS) / 2 : 0;     // number of pairs
    constexpr int TS = PS + 2 * NP;                          // tail scalar col
    float s = 0.f;
    if (S < PS) s += ex2_s(row[S]);                          // head scalar
    if (NP > 0) {
        const __half2* r2 = reinterpret_cast<const __half2*>(row + PS);
        __half2 acc = ex2_h2(r2[0]);
#pragma unroll
        for (int p = 1; p < NP; p++) acc = __hadd2(acc, ex2_h2(r2[p]));
        float2 f = __half22float2(acc);
        s += f.x + f.y;
    }
    if (TS < E) s += ex2_s(row[TS]);                         // tail scalar
    return __logf(s);
}

template <int P>
__device__ __forceinline__ float lse_row(const __half* row) {
    float a = 0.f;
    a += lse_seg< 1,  8, P>(row);
    a += lse_seg< 8, 24, P>(row);
    a += lse_seg<24, 31, P>(row);
    a += lse_seg<31, 45, P>(row);
    a += lse_seg<45, 51, P>(row);
    a += lse_seg<51, 53, P>(row);
    a += lse_seg<53, 55, P>(row);
    a += lse_seg<58, 99, P>(row);
    return a;
}

// ---------------- other helpers ---------------------------------------------
__device__ __forceinline__ bool quad_rare(int c0) {
    return (c0 == 0) | ((unsigned)(c0 - 52) <= 5u) | (c0 >= 96);
}
__device__ __forceinline__ int wrap99(int c) { return (c >= NCOLS) ? c - NCOLS : c; }

// consume one float4-pair: prescaled fp16 store + dotAll FFMAs + rare fixup
__device__ __forceinline__ void consume(
    float4 d, float4 t, int c0, __half* smh, int i,
    float& dot0, float& dot1, float& mse, float& dotc)
{
    const __half2 L2E = __float2half2_rn(1.44269504089f);
    union { __half2 h[2]; uint2 u; } pk;
    pk.h[0] = __hmul2(__floats2half2_rn(d.x, d.y), L2E);
    pk.h[1] = __hmul2(__floats2half2_rn(d.z, d.w), L2E);
    *reinterpret_cast<uint2*>(smh + 4 * i) = pk.u;   // 8B aligned
    dot0 = fmaf(d.x, t.x, dot0);
    dot1 = fmaf(d.y, t.y, dot1);
    dot0 = fmaf(d.z, t.z, dot0);
    dot1 = fmaf(d.w, t.w, dot1);
    if (quad_rare(c0)) {
        float dv[4] = {d.x, d.y, d.z, d.w};
        float tv[4] = {t.x, t.y, t.z, t.w};
        int c = c0;
#pragma unroll
        for (int j = 0; j < 4; j++) {
            bool cont = (c == 0) | ((unsigned)(c - 55) <= 2u);
            if (cont) {
                float df = dv[j] - tv[j];
                mse  = fmaf(df, df, mse);
                dotc = fmaf(dv[j], tv[j], dotc);   // subtract later
            }
            if (++c == NCOLS) c = 0;
        }
    }
}

// ---------------- fused kernel ---------------------------------------------
__global__ void __launch_bounds__(TPB, 8)
k_fused(const float4* __restrict__ e4,
        const float* __restrict__ dec, const float* __restrict__ tru,
        float* __restrict__ out, int B) {
    __shared__ __align__(8) __half smh[TILE * NCOLS];   // 25344 B (tile role)
    __shared__ float wr[3][TPB / 32];
    __shared__ int   s_last;
    __shared__ float s_mn[4][10], s_mx[4][10]; // prep role
    __shared__ unsigned sh[200];
    __shared__ float smn[10], swid[10];

    const int t = threadIdx.x, lane = t & 31, w = t >> 5;

    if (blockIdx.x < NPREP) {
        // ================= PREP ROLE =================
        const int stride = NPREP * TPB;
        const int gbase  = blockIdx.x * TPB + t;

        float mn[10], mx[10];
        const float INF = __int_as_float(0x7f800000);
#pragma unroll
        for (int i = 0; i < 10; i++) { mn[i] = INF; mx[i] = -INF; }
        for (int r = gbase; r < B; r += 2 * stride) {
            float4 a0 = e4[3*r], b0 = e4[3*r+1], c0 = e4[3*r+2];
            int r1 = r + stride;
            bool ok1 = r1 < B;
            float4 a1, b1, c1;
            if (ok1) { a1 = e4[3*r1]; b1 = e4[3*r1+1]; c1 = e4[3*r1+2]; }
            float v0[10] = {a0.x,a0.y,a0.z,a0.w,b0.x,b0.y,b0.z,b0.w,c0.x,c0.y};
#pragma unroll
            for (int i = 0; i < 10; i++) {
                mn[i] = fminf(mn[i], v0[i]);
                mx[i] = fmaxf(mx[i], v0[i]);
            }
            if (ok1) {
                float v1[10] = {a1.x,a1.y,a1.z,a1.w,b1.x,b1.y,b1.z,b1.w,c1.x,c1.y};
#pragma unroll
                for (int i = 0; i < 10; i++) {
                    mn[i] = fminf(mn[i], v1[i]);
                    mx[i] = fmaxf(mx[i], v1[i]);
                }
            }
        }
#pragma unroll
        for (int i = 0; i < 10; i++) {
#pragma unroll
            for (int o = 16; o > 0; o >>= 1) {
                mn[i] = fminf(mn[i], __shfl_xor_sync(0xFFFFFFFFu, mn[i], o));
                mx[i] = fmaxf(mx[i], __shfl_xor_sync(0xFFFFFFFFu, mx[i], o));
            }
        }
        if (lane == 0) {
#pragma unroll
            for (int i = 0; i < 10; i++) { s_mn[w][i] = mn[i]; s_mx[w][i] = mx[i]; }
        }
        for (int j = t; j < 200; j += TPB) sh[j] = 0u;
        __syncthreads();
        if (t < 10) {
            float m = s_mn[0][t], x = s_mx[0][t];
#pragma unroll
            for (int ww = 1; ww < 4; ww++) { m = fminf(m, s_mn[ww][t]); x = fmaxf(x, s_mx[ww][t]); }
            atomicMax(&gz.cominkey[t], ~f2key(m));
            atomicMax(&gz.maxkey[t],    f2key(x));
        }

        __threadfence();
        __syncthreads();
        if (t == 0) {
            atomicAdd(&gz.done[0], 1u);
            while (atomicAdd(&gz.done[0], 0u) < (unsigned)NPREP) __nanosleep(64);
        }
        __syncthreads();
        __threadfence();

        if (t < 10) {
            float m = key2f(~gz.cominkey[t]);
            float x = key2f( gz.maxkey[t]);
            smn[t]  = m;
            swid[t] = fmaxf(x - m, 1e-12f);
        }
        __syncthreads();

        const int B_al = B & ~31;
        for (int r = gbase; r < B_al; r += stride) {
            float4 a = e4[3*r], b = e4[3*r+1], c = e4[3*r+2];
            unsigned base = (c.w == 0.0f) ? 0u : 100u;   // col 11 = sex
            float v[10] = {a.x,a.y,a.z,a.w,b.x,b.y,b.z,b.w,c.x,c.y};
#pragma unroll
            for (int i = 0; i < 10; i++) {
                float tt = (v[i] - smn[i]) / swid[i] * 10.0f;
                int bi = (int)floorf(tt);
                bi = bi < 0 ? 0 : (bi > 9 ? 9 : bi);
                unsigned key = base + (unsigned)(i * 10 + bi);
                unsigned msk = __match_any_sync(0xFFFFFFFFu, key);
                if ((msk & ((1u << lane) - 1u)) == 0u)
                    atomicAdd(&sh[key], (unsigned)__popc(msk));
            }
        }
        for (int r = B_al + gbase; r < B; r += stride) {
            float4 a = e4[3*r], b = e4[3*r+1], c = e4[3*r+2];
            unsigned base = (c.w == 0.0f) ? 0u : 100u;
            float v[10] = {a.x,a.y,a.z,a.w,b.x,b.y,b.z,b.w,c.x,c.y};
#pragma unroll
            for (int i = 0; i < 10; i++) {
                float tt = (v[i] - smn[i]) / swid[i] * 10.0f;
                int bi = (int)floorf(tt);
                bi = bi < 0 ? 0 : (bi > 9 ? 9 : bi);
                atomicAdd(&sh[base + (unsigned)(i * 10 + bi)], 1u);
            }
        }
        __syncthreads();
        for (int j = t; j < 200; j += TPB)
            if (sh[j]) atomicAdd(&gz.hist[j], sh[j]);
        __threadfence();
        __syncthreads();
        if (t == 0) atomicAdd(&gz.done[2], 1u);   // hist ticket
        return;
    }

    // ================= TILE ROLE =================
    const int tileIdx = blockIdx.x - NPREP;
    const int NT      = gridDim.x - NPREP;
    const int r0   = tileIdx * TILE;
    const int rows = min(TILE, B - r0);
    const int nflt = rows * NCOLS;
    const int n4   = nflt >> 2;
    const size_t ebase = (size_t)r0 * NCOLS;
    const float4* d4 = (const float4*)(dec + ebase);
    const float4* t4 = (const float4*)(tru + ebase);

    float dot0 = 0.f, dot1 = 0.f, a_mse = 0.f, dotc = 0.f;

    // columns: element 4*(tid + j*TPB): +17 mod 99 per j, +34 per 2-pair stage
    int cb = (4 * t) % NCOLS;
    const int NS = n4 / (2 * TPB);           // full 2-pair stages

    float4 da0, ta0, da1, ta1, db0, tb0, db1, tb1;
    int ia = t;
    if (NS > 0) {
        da0 = d4[ia];       ta0 = t4[ia];
        da1 = d4[ia + TPB]; ta1 = t4[ia + TPB];
    }
    for (int s = 0; s < NS; s += 2) {
        const int ib = ia + 2 * TPB;
        const bool hb = (s + 1) < NS;
        if (hb) { db0 = d4[ib]; tb0 = t4[ib]; db1 = d4[ib + TPB]; tb1 = t4[ib + TPB]; }
        consume(da0, ta0, cb,              smh, ia,       dot0, dot1, a_mse, dotc);
        consume(da1, ta1, wrap99(cb + 17), smh, ia + TPB, dot0, dot1, a_mse, dotc);
        cb = wrap99(cb + 34);
        if (!hb) break;
        const int ic = ib + 2 * TPB;
        const bool hc = (s + 2) < NS;
        if (hc) { da0 = d4[ic]; ta0 = t4[ic]; da1 = d4[ic + TPB]; ta1 = t4[ic + TPB]; }
        consume(db0, tb0, cb,              smh, ib,       dot0, dot1, a_mse, dotc);
        consume(db1, tb1, wrap99(cb + 17), smh, ib + TPB, dot0, dot1, a_mse, dotc);
        cb = wrap99(cb + 34);
        ia = ic;
    }
    for (int i = NS * 2 * TPB + t; i < n4; i += TPB) {
        consume(d4[i], t4[i], (4 * i) % NCOLS, smh, i, dot0, dot1, a_mse, dotc);
    }
    for (int e = (n4 << 2) + t; e < nflt; e += TPB) {   // float tail
        float d = dec[ebase + e], tt = tru[ebase + e];
        smh[e] = __float2half_rn(d * 1.44269504089f);
        int c = e % NCOLS;
        bool cont = (c == 0) | ((unsigned)(c - 55) <= 2u);
        dot0 = fmaf(d, tt, dot0);
        if (cont) {
            float df = d - tt;
            a_mse = fmaf(df, df, a_mse);
            dotc  = fmaf(d, tt, dotc);
        }
    }
    __syncthreads();

    // phase 2: one thread per row, hardware-ex2 half2 LSE (parity-templated)
    float a_lse = 0.f;
    if (t < rows) {
        const __half* row = smh + t * NCOLS;
        if (t & 1) a_lse = lse_row<1>(row);
        else       a_lse = lse_row<0>(row);
    }

    // block reduce -> double global atomics
    float a_dot = (dot0 + dot1) - dotc;
#pragma unroll
    for (int o = 16; o > 0; o >>= 1) {
        a_mse += __shfl_xor_sync(0xFFFFFFFFu, a_mse, o);
        a_dot += __shfl_xor_sync(0xFFFFFFFFu, a_dot, o);
        a_lse += __shfl_xor_sync(0xFFFFFFFFu, a_lse, o);
    }
    if (lane == 0) { wr[0][w] = a_mse; wr[1][w] = a_dot; wr[2][w] = a_lse; }
    __syncthreads();
    if (t == 0) {
        float m = 0.f, d = 0.f, l = 0.f;
#pragma unroll
        for (int k = 0; k < TPB / 32; k++) { m += wr[0][k]; d += wr[1][k]; l += wr[2][k]; }
        atomicAdd(&gz.acc[0], (double)m);
        atomicAdd(&gz.acc[1], (double)d);
        atomicAdd(&gz.acc[2], (double)l);
        __threadfence();
        unsigned tk = atomicAdd(&gz.done[1], 1u);
        s_last = (tk == (unsigned)(NT - 1)) ? 1 : 0;
        if (s_last) {   // wait for prep histogram tickets
            while (atomicAdd(&gz.done[2], 0u) < (unsigned)NPREP) __nanosleep(64);
        }
    }
    __syncthreads();

    // last tile CTA finalizes (double precision, 32 lanes)
    if (s_last && t < 32) {
        __threadfence();
        int lane32 = t;
        double mcnt = (lane32 < 10) ? (double)gz.hist[lane32]       : 0.0;
        double fcnt = (lane32 < 10) ? (double)gz.hist[100 + lane32] : 0.0;
#pragma unroll
        for (int o = 16; o > 0; o >>= 1) {
            mcnt += __shfl_xor_sync(0xFFFFFFFFu, mcnt, o);
            fcnt += __shfl_xor_sync(0xFFFFFFFFu, fcnt, o);
        }
        double mc = fmax(mcnt, 1.0), fc = fmax(fcnt, 1.0);
        double kld = 0.0;
#pragma unroll
        for (int k = 0; k < 4; k++) {
            int b = k * 32 + lane32;
            if (b < 100) {
                double p = (double)gz.hist[b] / mc;
                double q = (double)gz.hist[100 + b] / fc;
                if (p > 0.0 && q > 0.0) kld += p * log(p / q);
            }
        }
#pragma unroll
        for (int o = 16; o > 0; o >>= 1)
            kld += __shfl_xor_sync(0xFFFFFFFFu, kld, o);
        if (lane32 == 0) {
            double mseS = atomicAdd(&gz.acc[0], 0.0);
            double dotS = atomicAdd(&gz.acc[1], 0.0);
            double lseS = atomicAdd(&gz.acc[2], 0.0);
            double fB   = (double)B;
            double mse  = mseS / fB;
            double ce   = (lseS - dotS) / fB;
            double akld = 0.5 * kld;
            out[0] = (float)(0.5 * (mse + ce) + akld);
            out[1] = (float)mse;
            out[2] = (float)ce;
            out[3] = (float)akld;
        }
    }
}

// ---------------- launcher ----------------
extern "C" void kernel_launch(void* const* d_in, const int* in_sizes, int n_in,
                              void* d_out, int out_size) {
    const float* enc = (const float*)d_in[0];   // [B,12]
    const float* dec = (const float*)d_in[1];   // [B,99]
    const float* tru = (const float*)d_in[2];   // [B,99]
    const int B = in_sizes[1] / NCOLS;
    float* out = (float*)d_out;

    void* pz = nullptr;
    cudaGetSymbolAddress(&pz, gz);
    cudaMemsetAsync(pz, 0, sizeof(Zeros), 0);

    cudaFuncSetAttribute(k_fused, cudaFuncAttributePreferredSharedMemoryCarveout, 100);

    const int NT   = (B + TILE - 1) / TILE;
    const int grid = NPREP + NT;
    k_fused<<<grid, TPB>>>((const float4*)enc, dec, tru, out, B);
}

// round 15
// speedup vs baseline: 1.3509x; 1.0615x over previous
#include <cuda_runtime.h>
#include <cuda_fp16.h>
#include <cstdint>

static constexpr int NCOLS = 99;
static constexpr int TPB   = 128;   // threads per block
static constexpr int TILE  = 128;   // rows per tile
static constexpr int NPREP = 296;   // prep-role CTAs (first in grid)
static constexpr int GRID  = 1184;  // 8 CTAs/SM x 148 SMs, persistent

// ---------------- device scratch (single memset(0), no allocation) ---------
struct Zeros {
    double   acc[3];        // [0]=mse sum, [1]=dot sum (ce cols), [2]=lse sum
    unsigned hist[200];     // [sex(2)][feat(10)][bin(10)]
    unsigned maxkey[10];    // atomicMax of key(x)
    unsigned cominkey[10];  // atomicMax of ~key(x)  (== complemented min)
    unsigned done[3];       // [0]: prep minmax sync, [1]: finalize ticket, [2]: prep hist done
    unsigned ticket;        // dynamic tile ticket
};
__device__ Zeros gz;

// monotonic float<->uint key
__device__ __forceinline__ unsigned f2key(float f) {
    unsigned u = __float_as_uint(f);
    return (u & 0x80000000u) ? ~u : (u | 0x80000000u);
}
__device__ __forceinline__ float key2f(unsigned k) {
    unsigned u = (k & 0x80000000u) ? (k ^ 0x80000000u) : ~k;
    return __uint_as_float(u);
}

// ---------------- helpers ---------------------------------------------------
template <int S, int E>
__device__ __forceinline__ float lse_blk_h(const __half* row) {
    float s = 0.f;
#pragma unroll
    for (int c = S; c < E; ++c) s += __expf(__half2float(row[c]));
    return __logf(s);
}

__device__ __forceinline__ bool quad_rare(int c0) {
    return (c0 == 0) | ((unsigned)(c0 - 52) <= 5u) | (c0 >= 96);
}
__device__ __forceinline__ int wrap99(int c) { return (c >= NCOLS) ? c - NCOLS : c; }

// consume one float4-pair: fp16 store + dotAll FFMAs + rare cont-col fixup
__device__ __forceinline__ void consume(
    float4 d, float4 t, int c0, __half* smh, int i,
    float& dot0, float& dot1, float& mse, float& dotc)
{
    union { __half2 h[2]; uint2 u; } pk;
    pk.h[0] = __floats2half2_rn(d.x, d.y);
    pk.h[1] = __floats2half2_rn(d.z, d.w);
    *reinterpret_cast<uint2*>(smh + 4 * i) = pk.u;   // 8B aligned
    dot0 = fmaf(d.x, t.x, dot0);
    dot1 = fmaf(d.y, t.y, dot1);
    dot0 = fmaf(d.z, t.z, dot0);
    dot1 = fmaf(d.w, t.w, dot1);
    if (quad_rare(c0)) {
        float dv[4] = {d.x, d.y, d.z, d.w};
        float tv[4] = {t.x, t.y, t.z, t.w};
        int c = c0;
#pragma unroll
        for (int j = 0; j < 4; j++) {
            bool cont = (c == 0) | ((unsigned)(c - 55) <= 2u);
            if (cont) {
                float df = dv[j] - tv[j];
                mse  = fmaf(df, df, mse);
                dotc = fmaf(dv[j], tv[j], dotc);   // subtract later
            }
            if (++c == NCOLS) c = 0;
        }
    }
}

// ---------------- fused persistent kernel ----------------------------------
__global__ void __launch_bounds__(TPB, 8)
k_fused(const float4* __restrict__ e4,
        const float* __restrict__ dec, const float* __restrict__ tru,
        float* __restrict__ out, int B) {
    __shared__ __align__(8) __half smh[TILE * NCOLS];   // 25344 B
    __shared__ float wr[3][TPB / 32];
    __shared__ int   s_last, s_next;
    __shared__ float s_mn[4][10], s_mx[4][10]; // prep role
    __shared__ unsigned sh[200];
    __shared__ float smn[10], swid[10];

    const int t = threadIdx.x, lane = t & 31, w = t >> 5;

    if (blockIdx.x < NPREP) {
        // ================= PREP ROLE (then joins tile stealing) ============
        const int stride = NPREP * TPB;
        const int gbase  = blockIdx.x * TPB + t;

        float mn[10], mx[10];
        const float INF = __int_as_float(0x7f800000);
#pragma unroll
        for (int i = 0; i < 10; i++) { mn[i] = INF; mx[i] = -INF; }
        for (int r = gbase; r < B; r += 2 * stride) {
            float4 a0 = e4[3*r], b0 = e4[3*r+1], c0 = e4[3*r+2];
            int r1 = r + stride;
            bool ok1 = r1 < B;
            float4 a1, b1, c1;
            if (ok1) { a1 = e4[3*r1]; b1 = e4[3*r1+1]; c1 = e4[3*r1+2]; }
            float v0[10] = {a0.x,a0.y,a0.z,a0.w,b0.x,b0.y,b0.z,b0.w,c0.x,c0.y};
#pragma unroll
            for (int i = 0; i < 10; i++) {
                mn[i] = fminf(mn[i], v0[i]);
                mx[i] = fmaxf(mx[i], v0[i]);
            }
            if (ok1) {
                float v1[10] = {a1.x,a1.y,a1.z,a1.w,b1.x,b1.y,b1.z,b1.w,c1.x,c1.y};
#pragma unroll
                for (int i = 0; i < 10; i++) {
                    mn[i] = fminf(mn[i], v1[i]);
                    mx[i] = fmaxf(mx[i], v1[i]);
                }
            }
        }
#pragma unroll
        for (int i = 0; i < 10; i++) {
#pragma unroll
            for (int o = 16; o > 0; o >>= 1) {
                mn[i] = fminf(mn[i], __shfl_xor_sync(0xFFFFFFFFu, mn[i], o));
                mx[i] = fmaxf(mx[i], __shfl_xor_sync(0xFFFFFFFFu, mx[i], o));
            }
        }
        if (lane == 0) {
#pragma unroll
            for (int i = 0; i < 10; i++) { s_mn[w][i] = mn[i]; s_mx[w][i] = mx[i]; }
        }
        for (int j = t; j < 200; j += TPB) sh[j] = 0u;
        __syncthreads();
        if (t < 10) {
            float m = s_mn[0][t], x = s_mx[0][t];
#pragma unroll
            for (int ww = 1; ww < 4; ww++) { m = fminf(m, s_mn[ww][t]); x = fmaxf(x, s_mx[ww][t]); }
            atomicMax(&gz.cominkey[t], ~f2key(m));
            atomicMax(&gz.maxkey[t],    f2key(x));
        }

        __threadfence();
        __syncthreads();
        if (t == 0) {
            atomicAdd(&gz.done[0], 1u);
            while (atomicAdd(&gz.done[0], 0u) < (unsigned)NPREP) __nanosleep(64);
        }
        __syncthreads();
        __threadfence();

        if (t < 10) {
            float m = key2f(~gz.cominkey[t]);
            float x = key2f( gz.maxkey[t]);
            smn[t]  = m;
            swid[t] = fmaxf(x - m, 1e-12f);
        }
        __syncthreads();

        const int B_al = B & ~31;
        for (int r = gbase; r < B_al; r += stride) {
            float4 a = e4[3*r], b = e4[3*r+1], c = e4[3*r+2];
            unsigned base = (c.w == 0.0f) ? 0u : 100u;   // col 11 = sex
            float v[10] = {a.x,a.y,a.z,a.w,b.x,b.y,b.z,b.w,c.x,c.y};
#pragma unroll
            for (int i = 0; i < 10; i++) {
                float tt = (v[i] - smn[i]) / swid[i] * 10.0f;
                int bi = (int)floorf(tt);
                bi = bi < 0 ? 0 : (bi > 9 ? 9 : bi);
                unsigned key = base + (unsigned)(i * 10 + bi);
                unsigned msk = __match_any_sync(0xFFFFFFFFu, key);
                if ((msk & ((1u << lane) - 1u)) == 0u)
                    atomicAdd(&sh[key], (unsigned)__popc(msk));
            }
        }
        for (int r = B_al + gbase; r < B; r += stride) {
            float4 a = e4[3*r], b = e4[3*r+1], c = e4[3*r+2];
            unsigned base = (c.w == 0.0f) ? 0u : 100u;
            float v[10] = {a.x,a.y,a.z,a.w,b.x,b.y,b.z,b.w,c.x,c.y};
#pragma unroll
            for (int i = 0; i < 10; i++) {
                float tt = (v[i] - smn[i]) / swid[i] * 10.0f;
                int bi = (int)floorf(tt);
                bi = bi < 0 ? 0 : (bi > 9 ? 9 : bi);
                atomicAdd(&sh[base + (unsigned)(i * 10 + bi)], 1u);
            }
        }
        __syncthreads();
        for (int j = t; j < 200; j += TPB)
            if (sh[j]) atomicAdd(&gz.hist[j], sh[j]);
        __threadfence();
        __syncthreads();
        if (t == 0) atomicAdd(&gz.done[2], 1u);   // hist ticket
        // fall through to tile stealing
    }

    // ================= PERSISTENT TILE STEALING =================
    const int NT = (B + TILE - 1) / TILE;
    float dot0 = 0.f, dot1 = 0.f, a_mse = 0.f, dotc = 0.f, a_lse = 0.f;
    const int cst = (4 * t) % NCOLS;

    while (true) {
        if (t == 0) s_next = (int)atomicAdd(&gz.ticket, 1u);
        __syncthreads();                  // also protects smh reuse across iters
        const int T = s_next;
        if (T >= NT) break;

        const int r0   = T * TILE;
        const int rows = min(TILE, B - r0);
        const int nflt = rows * NCOLS;
        const int n4   = nflt >> 2;
        const size_t ebase = (size_t)r0 * NCOLS;
        const float4* d4 = (const float4*)(dec + ebase);
        const float4* t4 = (const float4*)(tru + ebase);

        // phase 1: stream + stage fp16, 2-deep pipeline of 2-pair batches
        int cb = cst;
        const int NS = n4 / (2 * TPB);

        float4 da0, ta0, da1, ta1, db0, tb0, db1, tb1;
        int ia = t;
        if (NS > 0) {
            da0 = __ldcs(&d4[ia]);       ta0 = __ldcs(&t4[ia]);
            da1 = __ldcs(&d4[ia + TPB]); ta1 = __ldcs(&t4[ia + TPB]);
        }
        for (int s = 0; s < NS; s += 2) {
            const int ib = ia + 2 * TPB;
            const bool hb = (s + 1) < NS;
            if (hb) {
                db0 = __ldcs(&d4[ib]);       tb0 = __ldcs(&t4[ib]);
                db1 = __ldcs(&d4[ib + TPB]); tb1 = __ldcs(&t4[ib + TPB]);
            }
            consume(da0, ta0, cb,              smh, ia,       dot0, dot1, a_mse, dotc);
            consume(da1, ta1, wrap99(cb + 17), smh, ia + TPB, dot0, dot1, a_mse, dotc);
            cb = wrap99(cb + 34);
            if (!hb) break;
            const int ic = ib + 2 * TPB;
            const bool hc = (s + 2) < NS;
            if (hc) {
                da0 = __ldcs(&d4[ic]);       ta0 = __ldcs(&t4[ic]);
                da1 = __ldcs(&d4[ic + TPB]); ta1 = __ldcs(&t4[ic + TPB]);
            }
            consume(db0, tb0, cb,              smh, ib,       dot0, dot1, a_mse, dotc);
            consume(db1, tb1, wrap99(cb + 17), smh, ib + TPB, dot0, dot1, a_mse, dotc);
            cb = wrap99(cb + 34);
            ia = ic;
        }
        for (int i = NS * 2 * TPB + t; i < n4; i += TPB) {
            consume(__ldcs(&d4[i]), __ldcs(&t4[i]), (4 * i) % NCOLS,
                    smh, i, dot0, dot1, a_mse, dotc);
        }
        for (int e = (n4 << 2) + t; e < nflt; e += TPB) {   // float tail
            float d = dec[ebase + e], tt = tru[ebase + e];
            smh[e] = __float2half_rn(d);
            int c = e % NCOLS;
            bool cont = (c == 0) | ((unsigned)(c - 55) <= 2u);
            dot0 = fmaf(d, tt, dot0);
            if (cont) {
                float df = d - tt;
                a_mse = fmaf(df, df, a_mse);
                dotc  = fmaf(d, tt, dotc);
            }
        }
        __syncthreads();

        // phase 2: one thread per row, 8 block-LSEs from fp16 smem
        if (t < rows) {
            const __half* row = smh + t * NCOLS;
            a_lse += lse_blk_h< 1,  8>(row);
            a_lse += lse_blk_h< 8, 24>(row);
            a_lse += lse_blk_h<24, 31>(row);
            a_lse += lse_blk_h<31, 45>(row);
            a_lse += lse_blk_h<45, 51>(row);
            a_lse += lse_blk_h<51, 53>(row);
            a_lse += lse_blk_h<53, 55>(row);
            a_lse += lse_blk_h<58, 99>(row);
        }
        // loop-top __syncthreads orders these reads before next tile's writes
    }

    // ---- block reduce -> double global atomics ----
    float a_dot = (dot0 + dot1) - dotc;
#pragma unroll
    for (int o = 16; o > 0; o >>= 1) {
        a_mse += __shfl_xor_sync(0xFFFFFFFFu, a_mse, o);
        a_dot += __shfl_xor_sync(0xFFFFFFFFu, a_dot, o);
        a_lse += __shfl_xor_sync(0xFFFFFFFFu, a_lse, o);
    }
    if (lane == 0) { wr[0][w] = a_mse; wr[1][w] = a_dot; wr[2][w] = a_lse; }
    __syncthreads();
    if (t == 0) {
        float m = 0.f, d = 0.f, l = 0.f;
#pragma unroll
        for (int k = 0; k < TPB / 32; k++) { m += wr[0][k]; d += wr[1][k]; l += wr[2][k]; }
        atomicAdd(&gz.acc[0], (double)m);
        atomicAdd(&gz.acc[1], (double)d);
        atomicAdd(&gz.acc[2], (double)l);
        __threadfence();
        unsigned tk = atomicAdd(&gz.done[1], 1u);
        s_last = (tk == gridDim.x - 1u) ? 1 : 0;
        if (s_last) {   // wait for prep histogram tickets
            while (atomicAdd(&gz.done[2], 0u) < (unsigned)NPREP) __nanosleep(64);
        }
    }
    __syncthreads();

    // ---- last CTA finalizes (double precision, 32 lanes) ----
    if (s_last && t < 32) {
        __threadfence();
        int lane32 = t;
        double mcnt = (lane32 < 10) ? (double)gz.hist[lane32]       : 0.0;
        double fcnt = (lane32 < 10) ? (double)gz.hist[100 + lane32] : 0.0;
#pragma unroll
        for (int o = 16; o > 0; o >>= 1) {
            mcnt += __shfl_xor_sync(0xFFFFFFFFu, mcnt, o);
            fcnt += __shfl_xor_sync(0xFFFFFFFFu, fcnt, o);
        }
        double mc = fmax(mcnt, 1.0), fc = fmax(fcnt, 1.0);
        double kld = 0.0;
#pragma unroll
        for (int k = 0; k < 4; k++) {
            int b = k * 32 + lane32;
            if (b < 100) {
                double p = (double)gz.hist[b] / mc;
                double q = (double)gz.hist[100 + b] / fc;
                if (p > 0.0 && q > 0.0) kld += p * log(p / q);
            }
        }
#pragma unroll
        for (int o = 16; o > 0; o >>= 1)
            kld += __shfl_xor_sync(0xFFFFFFFFu, kld, o);
        if (lane32 == 0) {
            double mseS = atomicAdd(&gz.acc[0], 0.0);
            double dotS = atomicAdd(&gz.acc[1], 0.0);
            double lseS = atomicAdd(&gz.acc[2], 0.0);
            double fB   = (double)B;
            double mse  = mseS / fB;
            double ce   = (lseS - dotS) / fB;
            double akld = 0.5 * kld;
            out[0] = (float)(0.5 * (mse + ce) + akld);
            out[1] = (float)mse;
            out[2] = (float)ce;
            out[3] = (float)akld;
        }
    }
}

// ---------------- launcher ----------------
extern "C" void kernel_launch(void* const* d_in, const int* in_sizes, int n_in,
                              void* d_out, int out_size) {
    const float* enc = (const float*)d_in[0];   // [B,12]
    const float* dec = (const float*)d_in[1];   // [B,99]
    const float* tru = (const float*)d_in[2];   // [B,99]
    const int B = in_sizes[1] / NCOLS;
    float* out = (float*)d_out;

    void* pz = nullptr;
    cudaGetSymbolAddress(&pz, gz);
    cudaMemsetAsync(pz, 0, sizeof(Zeros), 0);

    cudaFuncSetAttribute(k_fused, cudaFuncAttributePreferredSharedMemoryCarveout, 100);

    k_fused<<<GRID, TPB>>>((const float4*)enc, dec, tru, out, B);
}